// round 8
// baseline (speedup 1.0000x reference)
#include <cuda_runtime.h>
#include <cuda_fp16.h>

#define NB 8
#define NC 16
#define NH 512
#define NW 512
#define NHW (NH * NW)

// Channel-last fp16 accumulator scratch: [B, H, W, C] halves = 67 MB.
// Static __device__ => zero-initialized at module load; k_transpose re-zeros
// it after reading, so it is zero again at the start of every invocation.
__device__ __half g_scr[(size_t)NB * NHW * NC];

// ---------------------------------------------------------------------------
// Kernel 1: forward-warp scatter. fp32 math, fp16 storage via v4.f16x2 REDs.
// 8 RED lane-ops per source = provable minimum (16B max RED width, 128B/src).
// ---------------------------------------------------------------------------
__device__ __forceinline__ unsigned pk(float a, float b) {
    __half2 h = __floats2half2_rn(a, b);
    return *reinterpret_cast<unsigned*>(&h);
}

__device__ __forceinline__ void red16h(__half* p, unsigned a, unsigned b,
                                       unsigned c, unsigned d) {
    asm volatile("red.global.add.noftz.v4.f16x2 [%0], {%1,%2,%3,%4};"
                 :: "l"(p), "r"(a), "r"(b), "r"(c), "r"(d) : "memory");
}

__device__ __forceinline__ void corner(__half* p, const float* v, float w) {
    red16h(p,
           pk(w * v[0], w * v[1]),  pk(w * v[2], w * v[3]),
           pk(w * v[4], w * v[5]),  pk(w * v[6], w * v[7]));
    red16h(p + 8,
           pk(w * v[8],  w * v[9]),  pk(w * v[10], w * v[11]),
           pk(w * v[12], w * v[13]), pk(w * v[14], w * v[15]));
}

__global__ void k_scatter(const float* __restrict__ im0,
                          const float* __restrict__ flow) {
    int x = blockIdx.x * blockDim.x + threadIdx.x;
    int y = blockIdx.y;
    int b = blockIdx.z;

    int pix = (b * NH + y) * NW + x;
    float2 f = __ldg((const float2*)flow + pix);

    float xd = (float)x + f.x;
    float yd = (float)y + f.y;
    float x0f = floorf(xd), y0f = floorf(yd);
    int x0 = (int)x0f, y0 = (int)y0f;

    // Reference semantics: scatter only if ALL four corners in-bounds
    if (x0 < 0 || x0 > NW - 2 || y0 < 0 || y0 > NH - 2) return;

    float fx = xd - x0f, fy = yd - y0f;
    float wnw = (1.f - fx) * (1.f - fy);
    float wne = fx * (1.f - fy);
    float wsw = (1.f - fx) * fy;
    float wse = fx * fy;

    float v[NC];
    const float* src = im0 + (size_t)b * NC * NHW + (size_t)y * NW + x;
#pragma unroll
    for (int c = 0; c < NC; ++c) v[c] = __ldg(src + (size_t)c * NHW);

    __half* nw = g_scr + ((size_t)(b * NH + y0) * NW + x0) * NC;
    __half* ne = nw + NC;
    __half* sw = nw + (size_t)NW * NC;
    __half* se = sw + NC;

    corner(nw, v, wnw);
    corner(ne, v, wne);
    corner(sw, v, wsw);
    corner(se, v, wse);
}

// ---------------------------------------------------------------------------
// Kernel 2: transpose fp16 [B,H,W,C] scratch -> fp32 [B,C,H,W] output (+im1),
// AND re-zero the scratch behind the read (replaces the standalone zero pass;
// the 67MB of zero-writes are L2-resident and hide under the DRAM phase).
// ---------------------------------------------------------------------------
__global__ void k_transpose(const float* __restrict__ im1,
                            float* __restrict__ out) {
    __shared__ float s[NC][257];
    int b = blockIdx.y;
    int pbase = blockIdx.x * 256;
    int t = threadIdx.x;

    // 256 pixels x 16 halves = 512 uint4; thread t handles uint4 #t and #(t+256)
    uint4* src = (uint4*)(g_scr + ((size_t)b * NHW + pbase) * NC);
    const uint4 z = make_uint4(0u, 0u, 0u, 0u);
#pragma unroll
    for (int i = 0; i < 2; ++i) {
        int j = t + i * 256;
        uint4 u = src[j];
        src[j] = z;                 // re-zero scratch for the next invocation
        int pl = j >> 1;            // pixel within tile
        int h0 = (j & 1) * 8;       // first channel in this 16B chunk
        const __half2* hp = (const __half2*)&u;
#pragma unroll
        for (int k = 0; k < 4; ++k) {
            float2 f2 = __half22float2(hp[k]);
            s[h0 + 2 * k][pl]     = f2.x;
            s[h0 + 2 * k + 1][pl] = f2.y;
        }
    }
    __syncthreads();

    size_t o = (size_t)b * NC * NHW + pbase + t;
#pragma unroll
    for (int c = 0; c < NC; ++c) {
        size_t idx = o + (size_t)c * NHW;
        out[idx] = s[c][t] + __ldg(im1 + idx);
    }
}

// ---------------------------------------------------------------------------
extern "C" void kernel_launch(void* const* d_in, const int* in_sizes, int n_in,
                              void* d_out, int out_size) {
    const float* im0  = (const float*)d_in[0];
    const float* flow = (const float*)d_in[1];
    const float* im1  = (const float*)d_in[2];
    float* out = (float*)d_out;

    k_scatter<<<dim3(NW / 256, NH, NB), 256>>>(im0, flow);
    k_transpose<<<dim3(NHW / 256, NB), 256>>>(im1, out);
}

// round 9
// speedup vs baseline: 1.2260x; 1.2260x over previous
#include <cuda_runtime.h>
#include <cuda_fp16.h>

#define NB 8
#define NC 16
#define NH 512
#define NW 512
#define NHW (NH * NW)

// Channel-last fp16 accumulator scratch: [B, H, W, C] halves = 67 MB.
// zero -> scatter -> transpose each iteration keeps it L2-resident.
__device__ __half g_scr[(size_t)NB * NHW * NC];

// ---------------------------------------------------------------------------
// Kernel 1: zero the scratch (67 MB as uint4)
// ---------------------------------------------------------------------------
__global__ void k_zero() {
    size_t i = (size_t)blockIdx.x * blockDim.x + threadIdx.x;
    ((uint4*)g_scr)[i] = make_uint4(0u, 0u, 0u, 0u);
}

// ---------------------------------------------------------------------------
// Kernel 2: forward-warp scatter. fp32 math, fp16 storage via v4.f16x2 REDs.
// 8 RED ops per source = floor (16B max RED width, 128B payload per source).
// ---------------------------------------------------------------------------
__device__ __forceinline__ unsigned pk(float a, float b) {
    __half2 h = __floats2half2_rn(a, b);
    return *reinterpret_cast<unsigned*>(&h);
}

__device__ __forceinline__ void red16h(__half* p, unsigned a, unsigned b,
                                       unsigned c, unsigned d) {
    asm volatile("red.global.add.noftz.v4.f16x2 [%0], {%1,%2,%3,%4};"
                 :: "l"(p), "r"(a), "r"(b), "r"(c), "r"(d) : "memory");
}

__device__ __forceinline__ void corner(__half* p, const float* v, float w) {
    red16h(p,
           pk(w * v[0], w * v[1]),  pk(w * v[2], w * v[3]),
           pk(w * v[4], w * v[5]),  pk(w * v[6], w * v[7]));
    red16h(p + 8,
           pk(w * v[8],  w * v[9]),  pk(w * v[10], w * v[11]),
           pk(w * v[12], w * v[13]), pk(w * v[14], w * v[15]));
}

__global__ void k_scatter(const float* __restrict__ im0,
                          const float* __restrict__ flow) {
    int x = blockIdx.x * blockDim.x + threadIdx.x;
    int y = blockIdx.y;
    int b = blockIdx.z;

    int pix = (b * NH + y) * NW + x;
    float2 f = __ldg((const float2*)flow + pix);

    float xd = (float)x + f.x;
    float yd = (float)y + f.y;
    float x0f = floorf(xd), y0f = floorf(yd);
    int x0 = (int)x0f, y0 = (int)y0f;

    // Reference semantics: scatter only if ALL four corners in-bounds
    if (x0 < 0 || x0 > NW - 2 || y0 < 0 || y0 > NH - 2) return;

    float fx = xd - x0f, fy = yd - y0f;
    float wnw = (1.f - fx) * (1.f - fy);
    float wne = fx * (1.f - fy);
    float wsw = (1.f - fx) * fy;
    float wse = fx * fy;

    float v[NC];
    const float* src = im0 + (size_t)b * NC * NHW + (size_t)y * NW + x;
#pragma unroll
    for (int c = 0; c < NC; ++c) v[c] = __ldg(src + (size_t)c * NHW);

    __half* nw = g_scr + ((size_t)(b * NH + y0) * NW + x0) * NC;
    __half* ne = nw + NC;
    __half* sw = nw + (size_t)NW * NC;
    __half* se = sw + NC;

    corner(nw, v, wnw);
    corner(ne, v, wne);
    corner(sw, v, wsw);
    corner(se, v, wse);
}

// ---------------------------------------------------------------------------
// Kernel 3: vectorized transpose. CTA = 1024 pixels; stage fp16 scratch as
// fp32 in smem (stride 1028 -> 16B-aligned float4 rows), then per channel do
// LDS.128 + LDG.128(im1) + STG.128(out): 4x fewer global instructions than
// the scalar version, 512B contiguous per warp access.
// ---------------------------------------------------------------------------
#define TPIX 1024
#define TSTR 1028
#define T_SMEM (NC * TSTR * 4)   // 65,792 B

__global__ __launch_bounds__(256) void k_transpose(const float* __restrict__ im1,
                                                   float* __restrict__ out) {
    extern __shared__ float s[];   // [NC][TSTR]
    int b = blockIdx.y;
    int pbase = blockIdx.x * TPIX;
    int t = threadIdx.x;

    // 1024 pixels x 16 halves = 2048 uint4; thread t handles 8 of them.
    const uint4* src = (const uint4*)(g_scr + ((size_t)b * NHW + pbase) * NC);
#pragma unroll
    for (int i = 0; i < 8; ++i) {
        int j = t + i * 256;
        uint4 u = __ldg(src + j);
        int pl = j >> 1;            // pixel within tile
        int h0 = (j & 1) * 8;       // first channel of this 16B chunk
        const __half2* hp = (const __half2*)&u;
#pragma unroll
        for (int k = 0; k < 4; ++k) {
            float2 f2 = __half22float2(hp[k]);
            s[(h0 + 2 * k) * TSTR + pl]     = f2.x;
            s[(h0 + 2 * k + 1) * TSTR + pl] = f2.y;
        }
    }
    __syncthreads();

    size_t obase = (size_t)b * NC * NHW + pbase + 4 * t;
#pragma unroll
    for (int c = 0; c < NC; ++c) {
        size_t idx = obase + (size_t)c * NHW;
        float4 a = *(const float4*)(s + c * TSTR + 4 * t);
        float4 m = __ldg((const float4*)(im1 + idx));
        a.x += m.x; a.y += m.y; a.z += m.z; a.w += m.w;
        *(float4*)(out + idx) = a;
    }
}

// ---------------------------------------------------------------------------
extern "C" void kernel_launch(void* const* d_in, const int* in_sizes, int n_in,
                              void* d_out, int out_size) {
    const float* im0  = (const float*)d_in[0];
    const float* flow = (const float*)d_in[1];
    const float* im1  = (const float*)d_in[2];
    float* out = (float*)d_out;

    cudaFuncSetAttribute(k_transpose,
                         cudaFuncAttributeMaxDynamicSharedMemorySize, T_SMEM);

    k_zero<<<16384, 256>>>();                       // 4,194,304 uint4
    k_scatter<<<dim3(NW / 256, NH, NB), 256>>>(im0, flow);
    k_transpose<<<dim3(NHW / TPIX, NB), 256, T_SMEM>>>(im1, out);
}

// round 10
// speedup vs baseline: 1.2263x; 1.0002x over previous
#include <cuda_runtime.h>
#include <cuda_fp16.h>

#define NB 8
#define NC 16
#define NH 512
#define NW 512
#define NHW (NH * NW)

// Channel-last fp16 accumulator scratch: [B, H, W, C] halves = 67 MB.
// Per-batch slices are independent: zero(b) -> scatter(b) -> transpose(b).
__device__ __half g_scr[(size_t)NB * NHW * NC];

// ---------------------------------------------------------------------------
// Kernel 1: zero one batch slice (8.4 MB as uint4)
// ---------------------------------------------------------------------------
__global__ void k_zero(int b) {
    size_t i = (size_t)blockIdx.x * blockDim.x + threadIdx.x;
    ((uint4*)(g_scr + (size_t)b * NHW * NC))[i] = make_uint4(0u, 0u, 0u, 0u);
}

// ---------------------------------------------------------------------------
// Kernel 2: forward-warp scatter for one batch. fp32 math, fp16 storage via
// v4.f16x2 REDs. 8 RED ops/source = floor (16B max RED width, 128B payload).
// ---------------------------------------------------------------------------
__device__ __forceinline__ unsigned pk(float a, float b) {
    __half2 h = __floats2half2_rn(a, b);
    return *reinterpret_cast<unsigned*>(&h);
}

__device__ __forceinline__ void red16h(__half* p, unsigned a, unsigned b,
                                       unsigned c, unsigned d) {
    asm volatile("red.global.add.noftz.v4.f16x2 [%0], {%1,%2,%3,%4};"
                 :: "l"(p), "r"(a), "r"(b), "r"(c), "r"(d) : "memory");
}

__device__ __forceinline__ void corner(__half* p, const float* v, float w) {
    red16h(p,
           pk(w * v[0], w * v[1]),  pk(w * v[2], w * v[3]),
           pk(w * v[4], w * v[5]),  pk(w * v[6], w * v[7]));
    red16h(p + 8,
           pk(w * v[8],  w * v[9]),  pk(w * v[10], w * v[11]),
           pk(w * v[12], w * v[13]), pk(w * v[14], w * v[15]));
}

__global__ void k_scatter(const float* __restrict__ im0,
                          const float* __restrict__ flow, int b) {
    int x = blockIdx.x * blockDim.x + threadIdx.x;
    int y = blockIdx.y;

    int pix = (b * NH + y) * NW + x;
    float2 f = __ldg((const float2*)flow + pix);

    float xd = (float)x + f.x;
    float yd = (float)y + f.y;
    float x0f = floorf(xd), y0f = floorf(yd);
    int x0 = (int)x0f, y0 = (int)y0f;

    // Reference semantics: scatter only if ALL four corners in-bounds
    if (x0 < 0 || x0 > NW - 2 || y0 < 0 || y0 > NH - 2) return;

    float fx = xd - x0f, fy = yd - y0f;
    float wnw = (1.f - fx) * (1.f - fy);
    float wne = fx * (1.f - fy);
    float wsw = (1.f - fx) * fy;
    float wse = fx * fy;

    float v[NC];
    const float* src = im0 + (size_t)b * NC * NHW + (size_t)y * NW + x;
#pragma unroll
    for (int c = 0; c < NC; ++c) v[c] = __ldg(src + (size_t)c * NHW);

    __half* nw = g_scr + ((size_t)(b * NH + y0) * NW + x0) * NC;
    __half* ne = nw + NC;
    __half* sw = nw + (size_t)NW * NC;
    __half* se = sw + NC;

    corner(nw, v, wnw);
    corner(ne, v, wne);
    corner(sw, v, wsw);
    corner(se, v, wse);
}

// ---------------------------------------------------------------------------
// Kernel 3: vectorized transpose for one batch: fp16 [H,W,C] slice -> fp32
// [C,H,W] output (+ im1). CTA = 1024 pixels staged through smem.
// ---------------------------------------------------------------------------
#define TPIX 1024
#define TSTR 1028
#define T_SMEM (NC * TSTR * 4)   // 65,792 B

__global__ __launch_bounds__(256) void k_transpose(const float* __restrict__ im1,
                                                   float* __restrict__ out, int b) {
    extern __shared__ float s[];   // [NC][TSTR]
    int pbase = blockIdx.x * TPIX;
    int t = threadIdx.x;

    const uint4* src = (const uint4*)(g_scr + ((size_t)b * NHW + pbase) * NC);
#pragma unroll
    for (int i = 0; i < 8; ++i) {
        int j = t + i * 256;
        uint4 u = __ldg(src + j);
        int pl = j >> 1;
        int h0 = (j & 1) * 8;
        const __half2* hp = (const __half2*)&u;
#pragma unroll
        for (int k = 0; k < 4; ++k) {
            float2 f2 = __half22float2(hp[k]);
            s[(h0 + 2 * k) * TSTR + pl]     = f2.x;
            s[(h0 + 2 * k + 1) * TSTR + pl] = f2.y;
        }
    }
    __syncthreads();

    size_t obase = (size_t)b * NC * NHW + pbase + 4 * t;
#pragma unroll
    for (int c = 0; c < NC; ++c) {
        size_t idx = obase + (size_t)c * NHW;
        float4 a = *(const float4*)(s + c * TSTR + 4 * t);
        float4 m = __ldg((const float4*)(im1 + idx));
        a.x += m.x; a.y += m.y; a.z += m.z; a.w += m.w;
        *(float4*)(out + idx) = a;
    }
}

// ---------------------------------------------------------------------------
// Two side streams, event-forked from the (captured) default stream so the
// per-batch pipelines overlap: transpose(b) [DRAM-bound] runs under
// scatter(b+1) [L2/RED-bound]; zero(b+1) hides under scatter(b).
// Streams/events are created once (resource setup only — no device memory).
// ---------------------------------------------------------------------------
struct PipeCtx {
    cudaStream_t s[2];
    cudaEvent_t fork;
    cudaEvent_t join[2];
    PipeCtx() {
        cudaStreamCreateWithFlags(&s[0], cudaStreamNonBlocking);
        cudaStreamCreateWithFlags(&s[1], cudaStreamNonBlocking);
        cudaEventCreateWithFlags(&fork,    cudaEventDisableTiming);
        cudaEventCreateWithFlags(&join[0], cudaEventDisableTiming);
        cudaEventCreateWithFlags(&join[1], cudaEventDisableTiming);
    }
};

extern "C" void kernel_launch(void* const* d_in, const int* in_sizes, int n_in,
                              void* d_out, int out_size) {
    const float* im0  = (const float*)d_in[0];
    const float* flow = (const float*)d_in[1];
    const float* im1  = (const float*)d_in[2];
    float* out = (float*)d_out;

    static PipeCtx ctx;   // created on first (non-captured) correctness call
    static bool attr_set = false;
    if (!attr_set) {
        cudaFuncSetAttribute(k_transpose,
                             cudaFuncAttributeMaxDynamicSharedMemorySize, T_SMEM);
        attr_set = true;
    }

    // fork both side streams off the default (capture) stream
    cudaEventRecord(ctx.fork, 0);
    cudaStreamWaitEvent(ctx.s[0], ctx.fork, 0);
    cudaStreamWaitEvent(ctx.s[1], ctx.fork, 0);

    for (int b = 0; b < NB; ++b) {
        cudaStream_t st = ctx.s[b & 1];
        k_zero<<<2048, 256, 0, st>>>(b);                       // 8.4MB slice
        k_scatter<<<dim3(NW / 256, NH), 256, 0, st>>>(im0, flow, b);
        k_transpose<<<NHW / TPIX, 256, T_SMEM, st>>>(im1, out, b);
    }

    // join back into the default stream
    cudaEventRecord(ctx.join[0], ctx.s[0]);
    cudaEventRecord(ctx.join[1], ctx.s[1]);
    cudaStreamWaitEvent(0, ctx.join[0], 0);
    cudaStreamWaitEvent(0, ctx.join[1], 0);
}

// round 11
// speedup vs baseline: 1.2621x; 1.0292x over previous
#include <cuda_runtime.h>
#include <cuda_fp16.h>

#define NB 8
#define NC 16
#define NH 512
#define NW 512
#define NHW (NH * NW)

// Channel-last fp16 accumulator scratch: [B, H, W, C] halves = 67 MB.
__device__ __half g_scr[(size_t)NB * NHW * NC];

// ---------------------------------------------------------------------------
// Kernel 1: monolithic zero of the scratch (67 MB as uint4) — 12us, L2-resident
// ---------------------------------------------------------------------------
__global__ void k_zero() {
    size_t i = (size_t)blockIdx.x * blockDim.x + threadIdx.x;
    ((uint4*)g_scr)[i] = make_uint4(0u, 0u, 0u, 0u);
}

// ---------------------------------------------------------------------------
// Kernel 2: forward-warp scatter for TWO batches (base, base+1).
// fp32 math, fp16 storage via v4.f16x2 REDs; 8 RED ops/source = floor.
// ---------------------------------------------------------------------------
__device__ __forceinline__ unsigned pk(float a, float b) {
    __half2 h = __floats2half2_rn(a, b);
    return *reinterpret_cast<unsigned*>(&h);
}

__device__ __forceinline__ void red16h(__half* p, unsigned a, unsigned b,
                                       unsigned c, unsigned d) {
    asm volatile("red.global.add.noftz.v4.f16x2 [%0], {%1,%2,%3,%4};"
                 :: "l"(p), "r"(a), "r"(b), "r"(c), "r"(d) : "memory");
}

__device__ __forceinline__ void corner(__half* p, const float* v, float w) {
    red16h(p,
           pk(w * v[0], w * v[1]),  pk(w * v[2], w * v[3]),
           pk(w * v[4], w * v[5]),  pk(w * v[6], w * v[7]));
    red16h(p + 8,
           pk(w * v[8],  w * v[9]),  pk(w * v[10], w * v[11]),
           pk(w * v[12], w * v[13]), pk(w * v[14], w * v[15]));
}

__global__ void k_scatter(const float* __restrict__ im0,
                          const float* __restrict__ flow, int base) {
    int x = blockIdx.x * blockDim.x + threadIdx.x;
    int y = blockIdx.y;
    int b = base + blockIdx.z;

    int pix = (b * NH + y) * NW + x;
    float2 f = __ldg((const float2*)flow + pix);

    float xd = (float)x + f.x;
    float yd = (float)y + f.y;
    float x0f = floorf(xd), y0f = floorf(yd);
    int x0 = (int)x0f, y0 = (int)y0f;

    // Reference semantics: scatter only if ALL four corners in-bounds
    if (x0 < 0 || x0 > NW - 2 || y0 < 0 || y0 > NH - 2) return;

    float fx = xd - x0f, fy = yd - y0f;
    float wnw = (1.f - fx) * (1.f - fy);
    float wne = fx * (1.f - fy);
    float wsw = (1.f - fx) * fy;
    float wse = fx * fy;

    float v[NC];
    const float* src = im0 + (size_t)b * NC * NHW + (size_t)y * NW + x;
#pragma unroll
    for (int c = 0; c < NC; ++c) v[c] = __ldg(src + (size_t)c * NHW);

    __half* nw = g_scr + ((size_t)(b * NH + y0) * NW + x0) * NC;
    __half* ne = nw + NC;
    __half* sw = nw + (size_t)NW * NC;
    __half* se = sw + NC;

    corner(nw, v, wnw);
    corner(ne, v, wne);
    corner(sw, v, wsw);
    corner(se, v, wse);
}

// ---------------------------------------------------------------------------
// Kernel 3: vectorized transpose for TWO batches: fp16 [H,W,C] -> fp32
// [C,H,W] (+ im1). CTA = 1024 pixels staged through smem.
// ---------------------------------------------------------------------------
#define TPIX 1024
#define TSTR 1028
#define T_SMEM (NC * TSTR * 4)   // 65,792 B

__global__ __launch_bounds__(256) void k_transpose(const float* __restrict__ im1,
                                                   float* __restrict__ out,
                                                   int base) {
    extern __shared__ float s[];   // [NC][TSTR]
    int b = base + blockIdx.y;
    int pbase = blockIdx.x * TPIX;
    int t = threadIdx.x;

    const uint4* src = (const uint4*)(g_scr + ((size_t)b * NHW + pbase) * NC);
#pragma unroll
    for (int i = 0; i < 8; ++i) {
        int j = t + i * 256;
        uint4 u = __ldg(src + j);
        int pl = j >> 1;
        int h0 = (j & 1) * 8;
        const __half2* hp = (const __half2*)&u;
#pragma unroll
        for (int k = 0; k < 4; ++k) {
            float2 f2 = __half22float2(hp[k]);
            s[(h0 + 2 * k) * TSTR + pl]     = f2.x;
            s[(h0 + 2 * k + 1) * TSTR + pl] = f2.y;
        }
    }
    __syncthreads();

    size_t obase = (size_t)b * NC * NHW + pbase + 4 * t;
#pragma unroll
    for (int c = 0; c < NC; ++c) {
        size_t idx = obase + (size_t)c * NHW;
        float4 a = *(const float4*)(s + c * TSTR + 4 * t);
        float4 m = __ldg((const float4*)(im1 + idx));
        a.x += m.x; a.y += m.y; a.z += m.z; a.w += m.w;
        *(float4*)(out + idx) = a;
    }
}

// ---------------------------------------------------------------------------
// Two side streams forked from the capture stream. s0: zero, S01, T01, S45,
// T45.  s1 (after zero): S23, T23, S67, T67.  Transposes (DRAM-bound) hide
// under the other stream's scatters (LTS-atomic-bound).
// ---------------------------------------------------------------------------
struct PipeCtx {
    cudaStream_t s[2];
    cudaEvent_t fork, zdone;
    cudaEvent_t join[2];
    PipeCtx() {
        cudaStreamCreateWithFlags(&s[0], cudaStreamNonBlocking);
        cudaStreamCreateWithFlags(&s[1], cudaStreamNonBlocking);
        cudaEventCreateWithFlags(&fork,    cudaEventDisableTiming);
        cudaEventCreateWithFlags(&zdone,   cudaEventDisableTiming);
        cudaEventCreateWithFlags(&join[0], cudaEventDisableTiming);
        cudaEventCreateWithFlags(&join[1], cudaEventDisableTiming);
    }
};

extern "C" void kernel_launch(void* const* d_in, const int* in_sizes, int n_in,
                              void* d_out, int out_size) {
    const float* im0  = (const float*)d_in[0];
    const float* flow = (const float*)d_in[1];
    const float* im1  = (const float*)d_in[2];
    float* out = (float*)d_out;

    static PipeCtx ctx;
    static bool attr_set = false;
    if (!attr_set) {
        cudaFuncSetAttribute(k_transpose,
                             cudaFuncAttributeMaxDynamicSharedMemorySize, T_SMEM);
        attr_set = true;
    }

    cudaEventRecord(ctx.fork, 0);
    cudaStreamWaitEvent(ctx.s[0], ctx.fork, 0);

    k_zero<<<16384, 256, 0, ctx.s[0]>>>();
    cudaEventRecord(ctx.zdone, ctx.s[0]);
    cudaStreamWaitEvent(ctx.s[1], ctx.zdone, 0);

    for (int p = 0; p < 4; ++p) {
        cudaStream_t st = ctx.s[p & 1];
        int base = 2 * p;
        k_scatter<<<dim3(NW / 256, NH, 2), 256, 0, st>>>(im0, flow, base);
        k_transpose<<<dim3(NHW / TPIX, 2), 256, T_SMEM, st>>>(im1, out, base);
    }

    cudaEventRecord(ctx.join[0], ctx.s[0]);
    cudaEventRecord(ctx.join[1], ctx.s[1]);
    cudaStreamWaitEvent(0, ctx.join[0], 0);
    cudaStreamWaitEvent(0, ctx.join[1], 0);
}